// round 12
// baseline (speedup 1.0000x reference)
#include <cuda_runtime.h>
#include <cstdint>
#include <math.h>

#define N_NODES 8192
#define FEAT    256
#define K1      25
#define K2      10

// Scratch (device globals — no allocation allowed)
__device__ int   g_nbr[N_NODES * K1];
__device__ int   g_cnt[N_NODES];
__device__ float g_s [N_NODES * FEAT];   // self branch:  lrelu(A@Wl^T + bl)
__device__ float g_yn[N_NODES * FEAT];   // raw nbr GEMM: A@Wn^T
__device__ float g_h1[N_NODES * FEAT];   // layer-1 output
__device__ float g_h2[N_NODES * FEAT];   // layer-2 output

// ---------------------------------------------------------------------------
// Kernel 1: first-K1 neighbor extraction (warp ballot prefix scan, early exit)
// ---------------------------------------------------------------------------
__global__ void nbr_kernel(const int* __restrict__ A) {
    int warp = (blockIdx.x * blockDim.x + threadIdx.x) >> 5;
    int lane = threadIdx.x & 31;
    if (warp >= N_NODES) return;
    const int* row = A + (size_t)warp * N_NODES;
    int found = 0;
    for (int c = 0; c < N_NODES && found < K1; c += 32) {
        int v = __ldg(row + c + lane);
        unsigned m = __ballot_sync(0xffffffffu, v > 0);
        if (v > 0) {
            int r = found + __popc(m & ((1u << lane) - 1u));
            if (r < K1) g_nbr[warp * K1 + r] = c + lane;
        }
        found += __popc(m);
    }
    int cnt = found < K1 ? found : K1;
    if (lane < K1 && lane >= cnt) g_nbr[warp * K1 + lane] = 0;  // safe dummy
    if (lane == 0) g_cnt[warp] = cnt;
}

__device__ __forceinline__ float lrelu(float x) {
    return x > 0.f ? x : 0.01f * x;
}

__device__ __forceinline__ unsigned f2tf(float x) {
    unsigned u;
    asm("cvt.rna.tf32.f32 %0, %1;" : "=r"(u) : "f"(x));
    return u;
}

__device__ __forceinline__ void mma_tf32(float* c,
    unsigned a0, unsigned a1, unsigned a2, unsigned a3,
    unsigned b0, unsigned b1)
{
    asm volatile(
        "mma.sync.aligned.m16n8k8.row.col.f32.tf32.tf32.f32 "
        "{%0,%1,%2,%3}, {%4,%5,%6,%7}, {%8,%9}, {%0,%1,%2,%3};"
        : "+f"(c[0]), "+f"(c[1]), "+f"(c[2]), "+f"(c[3])
        : "r"(a0), "r"(a1), "r"(a2), "r"(a3), "r"(b0), "r"(b1));
}

#define LDM_X4(r0, r1, r2, r3, addr)                                          \
    asm volatile("ldmatrix.sync.aligned.m8n8.x4.shared.b16 {%0,%1,%2,%3}, [%4];" \
        : "=r"(r0), "=r"(r1), "=r"(r2), "=r"(r3) : "r"(addr))

__device__ __forceinline__ void cp16(unsigned dst, const void* src) {
    asm volatile("cp.async.cg.shared.global [%0], [%1], 16;" :: "r"(dst), "l"(src));
}
__device__ __forceinline__ void cp_commit() {
    asm volatile("cp.async.commit_group;" ::: "memory");
}
__device__ __forceinline__ void cp_wait0() {
    asm volatile("cp.async.wait_group 0;" ::: "memory");
}

// ---------------------------------------------------------------------------
// Kernel 2: N-concatenated dual GEMM (one layer), both halves read the SAME A.
//   blockIdx.x < 4 : self half, W = Wl -> g_s  = lrelu(A@Wl^T + bl)
//   blockIdx.x >= 4: nbr  half, W = Wn -> g_yn = A@Wn^T          (raw)
// BM=128 BN=64 BK=32, 8 warps (4x2), warp tile 32x32, cp.async double buffer.
// Inner loop: ldmatrix.x4 (tf32-as-b16), 4 ldmatrix + 8 mma per k8.
// launch_bounds(256,4): ldmatrix loop needs ~64 regs -> 4 CTAs/SM, one wave.
// ---------------------------------------------------------------------------
template<int LAYER>
__global__ __launch_bounds__(256, 4) void gemm_dual(
    const float* __restrict__ X,
    const float* __restrict__ Wl, const float* __restrict__ bl,
    const float* __restrict__ Wn)
{
    constexpr int BM = 128, BN = 64, BK = 32, NIT = FEAT / BK;
    __shared__ __align__(16) unsigned sA[2][BM * BK];
    __shared__ __align__(16) unsigned sB[2][BN * BK];

    int tid = threadIdx.x;
    bool self = blockIdx.x < 4;
    int n0 = (blockIdx.x & 3) * BN;
    int m0 = blockIdx.y * BM;

    const float* Abase = (LAYER == 1) ? X : (const float*)g_h1;
    const float* W     = self ? Wl : Wn;
    float* Out         = self ? g_s : g_yn;

    // loader mapping: A 4 chunks/thread, B 2 chunks/thread (16B chunks)
    int am  = tid >> 1, akc = (tid & 1) * 4;
    int bn_ = tid >> 2, bkc = (tid & 3) * 2;
    const float* pA = Abase + (size_t)(m0 + am)  * FEAT + akc * 4;
    const float* pB = W     + (size_t)(n0 + bn_) * FEAT + bkc * 4;
    unsigned baseA = (unsigned)__cvta_generic_to_shared(&sA[0][0]);
    unsigned baseB = (unsigned)__cvta_generic_to_shared(&sB[0][0]);
    unsigned dA = baseA + am  * (BK * 4);
    unsigned dB = baseB + bn_ * (BK * 4);
    int aswz = am  & 7, bswz = bn_ & 7;

    // fragment ids
    int warp = tid >> 5, lane = tid & 31;
    int wm = (warp >> 1) * 32, wn = (warp & 1) * 32;
    int group = lane >> 2, tig = lane & 3;

    // ldmatrix per-lane row/chunk assignments (swizzle key = lane&7 for all)
    int lrowA = lane & 15;          // row within a 16-row block
    int lselA = lane >> 4;          // 0 -> chunk c, 1 -> chunk c+1
    int lswz  = lane & 7;
    unsigned rowBaseA0 = baseA + (unsigned)((wm +  0 + lrowA) * BK) * 4u;
    unsigned rowBaseA1 = baseA + (unsigned)((wm + 16 + lrowA) * BK) * 4u;
    unsigned rowBaseB  = baseB + (unsigned)((wn + lane) * BK) * 4u;

    float acc[2][4][4];
#pragma unroll
    for (int i = 0; i < 2; i++)
#pragma unroll
        for (int j = 0; j < 4; j++)
#pragma unroll
            for (int l = 0; l < 4; l++) acc[i][j][l] = 0.f;

#define ISSUE(st, k0)                                                          \
    {                                                                          \
        unsigned oa = dA + (st) * (BM * BK * 4);                               \
        const float* ga = pA + (k0);                                           \
        _Pragma("unroll")                                                      \
        for (int j = 0; j < 4; j++)                                            \
            cp16(oa + (((akc + j) ^ aswz) << 4), ga + j * 4);                  \
        unsigned ob = dB + (st) * (BN * BK * 4);                               \
        const float* gb = pB + (k0);                                           \
        _Pragma("unroll")                                                      \
        for (int j = 0; j < 2; j++)                                            \
            cp16(ob + (((bkc + j) ^ bswz) << 4), gb + j * 4);                  \
        cp_commit();                                                           \
    }

    ISSUE(0, 0);

    int st = 0;
    for (int it = 0; it < NIT; it++) {
        cp_wait0();
        __syncthreads();
        if (it + 1 < NIT) ISSUE(st ^ 1, (it + 1) * BK);
        unsigned stA = (unsigned)st * (BM * BK * 4);
        unsigned stB = (unsigned)st * (BN * BK * 4);
#pragma unroll
        for (int kk = 0; kk < BK; kk += 8) {
            int c0 = kk >> 2;
            unsigned af[2][4], bf0[4], bf1[4];
            LDM_X4(af[0][0], af[0][1], af[0][2], af[0][3],
                   rowBaseA0 + stA + (unsigned)(((c0 + lselA) ^ lswz) << 4));
            LDM_X4(af[1][0], af[1][1], af[1][2], af[1][3],
                   rowBaseA1 + stA + (unsigned)(((c0 + lselA) ^ lswz) << 4));
            LDM_X4(bf0[0], bf0[1], bf0[2], bf0[3],
                   rowBaseB + stB + (unsigned)((c0 ^ lswz) << 4));
            LDM_X4(bf1[0], bf1[1], bf1[2], bf1[3],
                   rowBaseB + stB + (unsigned)(((c0 + 1) ^ lswz) << 4));
#pragma unroll
            for (int mi = 0; mi < 2; mi++)
#pragma unroll
                for (int ni = 0; ni < 4; ni++)
                    mma_tf32(acc[mi][ni], af[mi][0], af[mi][1], af[mi][2], af[mi][3],
                             bf0[ni], bf1[ni]);
        }
        st ^= 1;
    }

    // epilogue: self half gets bias+lrelu, yn half is raw
#pragma unroll
    for (int mi = 0; mi < 2; mi++) {
#pragma unroll
        for (int half = 0; half < 2; half++) {
            int row = m0 + wm + mi * 16 + group + half * 8;
#pragma unroll
            for (int ni = 0; ni < 4; ni++) {
                int col = n0 + wn + ni * 8 + tig * 2;
                float v0 = acc[mi][ni][half * 2 + 0];
                float v1 = acc[mi][ni][half * 2 + 1];
                if (self) {
                    v0 = lrelu(v0 + __ldg(bl + col));
                    v1 = lrelu(v1 + __ldg(bl + col + 1));
                }
                *(float2*)(Out + (size_t)row * FEAT + col) = make_float2(v0, v1);
            }
        }
    }
#undef ISSUE
}

// ---------------------------------------------------------------------------
// Kernel 3: gather-mean over first min(cnt,K) rows of g_yn + bias + lrelu,
// combined with the self branch:  h = g_s + (cnt>0 ? lrelu(mean + bn) : 0).
// 4 nodes / 256-thread block, float4/thread, dual accumulators (R4 version).
// ---------------------------------------------------------------------------
template <int K>
__global__ __launch_bounds__(256) void comb_kernel(
    const float* __restrict__ bn, float* __restrict__ OutH)
{
    int node = blockIdx.x * 4 + (threadIdx.x >> 6);
    int c4   = (threadIdx.x & 63) << 2;
    int cnt = g_cnt[node]; if (cnt > K) cnt = K;
    const int* nb = g_nbr + node * K1;

    int idx[K];
#pragma unroll
    for (int t = 0; t < K; t++) idx[t] = __ldg(nb + t);

    float4 a0 = make_float4(0.f, 0.f, 0.f, 0.f);
    float4 a1 = make_float4(0.f, 0.f, 0.f, 0.f);
#pragma unroll
    for (int t = 0; t < K; t += 2) {
        if (t < cnt) {
            float4 v = *(const float4*)(g_yn + (size_t)idx[t] * FEAT + c4);
            a0.x += v.x; a0.y += v.y; a0.z += v.z; a0.w += v.w;
        }
        if (t + 1 < cnt) {
            float4 v = *(const float4*)(g_yn + (size_t)idx[t + 1] * FEAT + c4);
            a1.x += v.x; a1.y += v.y; a1.z += v.z; a1.w += v.w;
        }
    }
    float inv = (cnt > 0) ? (1.0f / (float)cnt) : 0.f;
    float4 b4 = *(const float4*)(bn + c4);
    float4 s4 = *(const float4*)(g_s + (size_t)node * FEAT + c4);
    float4 o;
    if (cnt > 0) {
        o.x = s4.x + lrelu((a0.x + a1.x) * inv + b4.x);
        o.y = s4.y + lrelu((a0.y + a1.y) * inv + b4.y);
        o.z = s4.z + lrelu((a0.z + a1.z) * inv + b4.z);
        o.w = s4.w + lrelu((a0.w + a1.w) * inv + b4.w);
    } else {
        o = s4;
    }
    *(float4*)(OutH + (size_t)node * FEAT + c4) = o;
}

// ---------------------------------------------------------------------------
// Kernel 4: final GEMM [8192,256]x[256,64] (tf32 mma) + fused log_softmax.
// BM=128 covers full C=64 per CTA (R4 version, 256 threads).
// ---------------------------------------------------------------------------
__global__ __launch_bounds__(256) void final_kernel(
    const float* __restrict__ W3, const float* __restrict__ b3,
    float* __restrict__ OutP)
{
    constexpr int BM = 128, BN = 64, BK = 16;
    const float* __restrict__ H = (const float*)g_h2;

    __shared__ unsigned sA[BK][BM];
    __shared__ unsigned sB[BK][BN];
    __shared__ float sRes[BM][BN + 1];
    __shared__ float sLse[BM];

    int tid = threadIdx.x;
    int m0 = blockIdx.x * BM;
    int am = tid & 127, ak = (tid >> 7) * 8;
    int bn = tid & 63,  bk = (tid >> 6) * 4;
    const float* pA = H  + (size_t)(m0 + am) * FEAT + ak;
    const float* pB = W3 + (size_t)bn * FEAT + bk;

    int warp = tid >> 5, lane = tid & 31;
    int wm = (warp >> 1) * 32, wn = (warp & 1) * 32;
    int group = lane >> 2, tig = lane & 3;
    int sw = tig << 3;

    float acc[2][4][4];
#pragma unroll
    for (int i = 0; i < 2; i++)
#pragma unroll
        for (int j = 0; j < 4; j++)
#pragma unroll
            for (int l = 0; l < 4; l++) acc[i][j][l] = 0.f;

    for (int k0 = 0; k0 < FEAT; k0 += BK) {
        float4 a0v = *(const float4*)(pA + k0);
        float4 a1v = *(const float4*)(pA + k0 + 4);
        float4 bv  = *(const float4*)(pB + k0);
        __syncthreads();
        sA[ak + 0][am ^ 0 ] = f2tf(a0v.x); sA[ak + 1][am ^ 8 ] = f2tf(a0v.y);
        sA[ak + 2][am ^ 16] = f2tf(a0v.z); sA[ak + 3][am ^ 24] = f2tf(a0v.w);
        sA[ak + 4][am ^ 0 ] = f2tf(a1v.x); sA[ak + 5][am ^ 8 ] = f2tf(a1v.y);
        sA[ak + 6][am ^ 16] = f2tf(a1v.z); sA[ak + 7][am ^ 24] = f2tf(a1v.w);
        sB[bk + 0][bn ^ 0 ] = f2tf(bv.x);  sB[bk + 1][bn ^ 8 ] = f2tf(bv.y);
        sB[bk + 2][bn ^ 16] = f2tf(bv.z);  sB[bk + 3][bn ^ 24] = f2tf(bv.w);
        __syncthreads();
#pragma unroll
        for (int kk = 0; kk < BK; kk += 8) {
            int kA = kk + tig;
            unsigned af[2][4], bf[4][2];
#pragma unroll
            for (int mi = 0; mi < 2; mi++) {
                int r = wm + mi * 16 + group;
                af[mi][0] = sA[kA    ][r       ^ sw];
                af[mi][1] = sA[kA    ][(r + 8) ^ sw];
                af[mi][2] = sA[kA + 4][r       ^ sw];
                af[mi][3] = sA[kA + 4][(r + 8) ^ sw];
            }
#pragma unroll
            for (int ni = 0; ni < 4; ni++) {
                int c = (wn + ni * 8 + group) ^ sw;
                bf[ni][0] = sB[kA    ][c];
                bf[ni][1] = sB[kA + 4][c];
            }
#pragma unroll
            for (int mi = 0; mi < 2; mi++)
#pragma unroll
                for (int ni = 0; ni < 4; ni++)
                    mma_tf32(acc[mi][ni], af[mi][0], af[mi][1], af[mi][2], af[mi][3],
                             bf[ni][0], bf[ni][1]);
        }
    }

#pragma unroll
    for (int mi = 0; mi < 2; mi++)
#pragma unroll
        for (int half = 0; half < 2; half++) {
            int r = wm + mi * 16 + group + half * 8;
#pragma unroll
            for (int ni = 0; ni < 4; ni++) {
                int col = wn + ni * 8 + tig * 2;
                sRes[r][col]     = acc[mi][ni][half * 2 + 0] + __ldg(b3 + col);
                sRes[r][col + 1] = acc[mi][ni][half * 2 + 1] + __ldg(b3 + col + 1);
            }
        }
    __syncthreads();

    if (tid < BM) {
        float mx = -1e30f;
#pragma unroll 8
        for (int c = 0; c < 64; c++) mx = fmaxf(mx, sRes[tid][c]);
        float s = 0.f;
#pragma unroll 8
        for (int c = 0; c < 64; c++) s += expf(sRes[tid][c] - mx);
        sLse[tid] = mx + logf(s);
    }
    __syncthreads();

    for (int idx = tid; idx < BM * 64; idx += 256) {
        int r = idx >> 6, c = idx & 63;
        OutP[(size_t)(m0 + r) * 64 + c] = sRes[r][c] - sLse[r];
    }
}

// ---------------------------------------------------------------------------
extern "C" void kernel_launch(void* const* d_in, const int* in_sizes, int n_in,
                              void* d_out, int out_size) {
    const float* X   = (const float*)d_in[0];
    const int*   A   = (const int*)  d_in[1];
    const float* Wn1 = (const float*)d_in[2];
    const float* bn1 = (const float*)d_in[3];
    const float* Wl1 = (const float*)d_in[4];
    const float* bl1 = (const float*)d_in[5];
    const float* Wn2 = (const float*)d_in[6];
    const float* bn2 = (const float*)d_in[7];
    const float* Wl2 = (const float*)d_in[8];
    const float* bl2 = (const float*)d_in[9];
    const float* W3  = (const float*)d_in[10];
    const float* b3  = (const float*)d_in[11];
    float* out = (float*)d_out;

    float* h1p; cudaGetSymbolAddress((void**)&h1p, g_h1);
    float* h2p; cudaGetSymbolAddress((void**)&h2p, g_h2);

    dim3 ggrid(8, N_NODES / 128);   // 8 n-tiles (4 self + 4 yn) x 64 m-tiles

    // layer 1 GEMM depends only on X -> launch first
    gemm_dual<1><<<ggrid, 256>>>(X, Wl1, bl1, Wn1);
    nbr_kernel<<<N_NODES / 8, 256>>>(A);
    comb_kernel<K1><<<N_NODES / 4, 256>>>(bn1, h1p);

    // layer 2
    gemm_dual<2><<<ggrid, 256>>>(X, Wl2, bl2, Wn2);
    comb_kernel<K2><<<N_NODES / 4, 256>>>(bn2, h2p);

    // classifier + log_softmax
    final_kernel<<<N_NODES / 128, 256>>>(W3, b3, out);
}

// round 14
// speedup vs baseline: 1.0940x; 1.0940x over previous
#include <cuda_runtime.h>
#include <cstdint>
#include <math.h>

#define N_NODES 8192
#define FEAT    256
#define K1      25
#define K2      10

// Scratch (device globals — no allocation allowed)
__device__ int   g_nbr[N_NODES * K1];
__device__ int   g_cnt[N_NODES];
__device__ float g_s [N_NODES * FEAT];   // self branch:  lrelu(A@Wl^T + bl)
__device__ float g_yn[N_NODES * FEAT];   // raw nbr GEMM: A@Wn^T
__device__ float g_h1[N_NODES * FEAT];   // layer-1 output
__device__ float g_h2[N_NODES * FEAT];   // layer-2 output

// ---------------------------------------------------------------------------
// Kernel 1: first-K1 neighbor extraction (warp ballot prefix scan, early exit)
// ---------------------------------------------------------------------------
__global__ void nbr_kernel(const int* __restrict__ A) {
    int warp = (blockIdx.x * blockDim.x + threadIdx.x) >> 5;
    int lane = threadIdx.x & 31;
    if (warp >= N_NODES) return;
    const int* row = A + (size_t)warp * N_NODES;
    int found = 0;
    for (int c = 0; c < N_NODES && found < K1; c += 32) {
        int v = __ldg(row + c + lane);
        unsigned m = __ballot_sync(0xffffffffu, v > 0);
        if (v > 0) {
            int r = found + __popc(m & ((1u << lane) - 1u));
            if (r < K1) g_nbr[warp * K1 + r] = c + lane;
        }
        found += __popc(m);
    }
    int cnt = found < K1 ? found : K1;
    if (lane < K1 && lane >= cnt) g_nbr[warp * K1 + lane] = 0;  // safe dummy
    if (lane == 0) g_cnt[warp] = cnt;
}

__device__ __forceinline__ float lrelu(float x) {
    return x > 0.f ? x : 0.01f * x;
}

__device__ __forceinline__ unsigned f2tf(float x) {
    unsigned u;
    asm("cvt.rna.tf32.f32 %0, %1;" : "=r"(u) : "f"(x));
    return u;
}

__device__ __forceinline__ void mma_tf32(float* c,
    unsigned a0, unsigned a1, unsigned a2, unsigned a3,
    unsigned b0, unsigned b1)
{
    asm volatile(
        "mma.sync.aligned.m16n8k8.row.col.f32.tf32.tf32.f32 "
        "{%0,%1,%2,%3}, {%4,%5,%6,%7}, {%8,%9}, {%0,%1,%2,%3};"
        : "+f"(c[0]), "+f"(c[1]), "+f"(c[2]), "+f"(c[3])
        : "r"(a0), "r"(a1), "r"(a2), "r"(a3), "r"(b0), "r"(b1));
}

#define LDM_X4(r0, r1, r2, r3, addr)                                          \
    asm volatile("ldmatrix.sync.aligned.m8n8.x4.shared.b16 {%0,%1,%2,%3}, [%4];" \
        : "=r"(r0), "=r"(r1), "=r"(r2), "=r"(r3) : "r"(addr))

__device__ __forceinline__ void cp16(unsigned dst, const void* src) {
    asm volatile("cp.async.cg.shared.global [%0], [%1], 16;" :: "r"(dst), "l"(src));
}
__device__ __forceinline__ void cp_commit() {
    asm volatile("cp.async.commit_group;" ::: "memory");
}
__device__ __forceinline__ void cp_wait0() {
    asm volatile("cp.async.wait_group 0;" ::: "memory");
}

// ---------------------------------------------------------------------------
// Kernel 2: N-concatenated dual GEMM (one layer), both halves read the SAME A.
//   blockIdx.x < 4 : self half, W = Wl -> g_s  = lrelu(A@Wl^T + bl)
//   blockIdx.x >= 4: nbr  half, W = Wn -> g_yn = A@Wn^T          (raw)
// BM=128 BN=64 BK=32, 8 warps (4x2), warp tile 32x32, cp.async double buffer.
// Inner loop: ldmatrix.x4 (tf32-as-b16), 4 ldmatrix + 8 mma per k8.
// Plain launch_bounds(256): 80 regs / 3 CTAs per SM is this kernel's optimum.
// ---------------------------------------------------------------------------
template<int LAYER>
__global__ __launch_bounds__(256) void gemm_dual(
    const float* __restrict__ X,
    const float* __restrict__ Wl, const float* __restrict__ bl,
    const float* __restrict__ Wn)
{
    constexpr int BM = 128, BN = 64, BK = 32, NIT = FEAT / BK;
    __shared__ __align__(16) unsigned sA[2][BM * BK];
    __shared__ __align__(16) unsigned sB[2][BN * BK];

    int tid = threadIdx.x;
    bool self = blockIdx.x < 4;
    int n0 = (blockIdx.x & 3) * BN;
    int m0 = blockIdx.y * BM;

    const float* Abase = (LAYER == 1) ? X : (const float*)g_h1;
    const float* W     = self ? Wl : Wn;
    float* Out         = self ? g_s : g_yn;

    // loader mapping: A 4 chunks/thread, B 2 chunks/thread (16B chunks)
    int am  = tid >> 1, akc = (tid & 1) * 4;
    int bn_ = tid >> 2, bkc = (tid & 3) * 2;
    const float* pA = Abase + (size_t)(m0 + am)  * FEAT + akc * 4;
    const float* pB = W     + (size_t)(n0 + bn_) * FEAT + bkc * 4;
    unsigned baseA = (unsigned)__cvta_generic_to_shared(&sA[0][0]);
    unsigned baseB = (unsigned)__cvta_generic_to_shared(&sB[0][0]);
    unsigned dA = baseA + am  * (BK * 4);
    unsigned dB = baseB + bn_ * (BK * 4);
    int aswz = am  & 7, bswz = bn_ & 7;

    // fragment ids
    int warp = tid >> 5, lane = tid & 31;
    int wm = (warp >> 1) * 32, wn = (warp & 1) * 32;
    int group = lane >> 2, tig = lane & 3;

    // ldmatrix per-lane row/chunk assignments (swizzle key = lane&7 for all)
    int lrowA = lane & 15;          // row within a 16-row block
    int lselA = lane >> 4;          // 0 -> chunk c, 1 -> chunk c+1
    int lswz  = lane & 7;
    unsigned rowBaseA0 = baseA + (unsigned)((wm +  0 + lrowA) * BK) * 4u;
    unsigned rowBaseA1 = baseA + (unsigned)((wm + 16 + lrowA) * BK) * 4u;
    unsigned rowBaseB  = baseB + (unsigned)((wn + lane) * BK) * 4u;

    float acc[2][4][4];
#pragma unroll
    for (int i = 0; i < 2; i++)
#pragma unroll
        for (int j = 0; j < 4; j++)
#pragma unroll
            for (int l = 0; l < 4; l++) acc[i][j][l] = 0.f;

#define ISSUE(st, k0)                                                          \
    {                                                                          \
        unsigned oa = dA + (st) * (BM * BK * 4);                               \
        const float* ga = pA + (k0);                                           \
        _Pragma("unroll")                                                      \
        for (int j = 0; j < 4; j++)                                            \
            cp16(oa + (((akc + j) ^ aswz) << 4), ga + j * 4);                  \
        unsigned ob = dB + (st) * (BN * BK * 4);                               \
        const float* gb = pB + (k0);                                           \
        _Pragma("unroll")                                                      \
        for (int j = 0; j < 2; j++)                                            \
            cp16(ob + (((bkc + j) ^ bswz) << 4), gb + j * 4);                  \
        cp_commit();                                                           \
    }

    ISSUE(0, 0);

    int st = 0;
    for (int it = 0; it < NIT; it++) {
        cp_wait0();
        __syncthreads();
        if (it + 1 < NIT) ISSUE(st ^ 1, (it + 1) * BK);
        unsigned stA = (unsigned)st * (BM * BK * 4);
        unsigned stB = (unsigned)st * (BN * BK * 4);
#pragma unroll
        for (int kk = 0; kk < BK; kk += 8) {
            int c0 = kk >> 2;
            unsigned af[2][4], bf0[4], bf1[4];
            LDM_X4(af[0][0], af[0][1], af[0][2], af[0][3],
                   rowBaseA0 + stA + (unsigned)(((c0 + lselA) ^ lswz) << 4));
            LDM_X4(af[1][0], af[1][1], af[1][2], af[1][3],
                   rowBaseA1 + stA + (unsigned)(((c0 + lselA) ^ lswz) << 4));
            LDM_X4(bf0[0], bf0[1], bf0[2], bf0[3],
                   rowBaseB + stB + (unsigned)((c0 ^ lswz) << 4));
            LDM_X4(bf1[0], bf1[1], bf1[2], bf1[3],
                   rowBaseB + stB + (unsigned)(((c0 + 1) ^ lswz) << 4));
#pragma unroll
            for (int mi = 0; mi < 2; mi++)
#pragma unroll
                for (int ni = 0; ni < 4; ni++)
                    mma_tf32(acc[mi][ni], af[mi][0], af[mi][1], af[mi][2], af[mi][3],
                             bf0[ni], bf1[ni]);
        }
        st ^= 1;
    }

    // epilogue: self half gets bias+lrelu, yn half is raw
#pragma unroll
    for (int mi = 0; mi < 2; mi++) {
#pragma unroll
        for (int half = 0; half < 2; half++) {
            int row = m0 + wm + mi * 16 + group + half * 8;
#pragma unroll
            for (int ni = 0; ni < 4; ni++) {
                int col = n0 + wn + ni * 8 + tig * 2;
                float v0 = acc[mi][ni][half * 2 + 0];
                float v1 = acc[mi][ni][half * 2 + 1];
                if (self) {
                    v0 = lrelu(v0 + __ldg(bl + col));
                    v1 = lrelu(v1 + __ldg(bl + col + 1));
                }
                *(float2*)(Out + (size_t)row * FEAT + col) = make_float2(v0, v1);
            }
        }
    }
#undef ISSUE
}

// ---------------------------------------------------------------------------
// Kernel 3: gather-mean over first min(cnt,K) rows of g_yn + bias + lrelu,
// combined with the self branch:  h = g_s + (cnt>0 ? lrelu(mean + bn) : 0).
// 4 nodes / 256-thread block, float4/thread, dual accumulators (R4 version).
// ---------------------------------------------------------------------------
template <int K>
__global__ __launch_bounds__(256) void comb_kernel(
    const float* __restrict__ bn, float* __restrict__ OutH)
{
    int node = blockIdx.x * 4 + (threadIdx.x >> 6);
    int c4   = (threadIdx.x & 63) << 2;
    int cnt = g_cnt[node]; if (cnt > K) cnt = K;
    const int* nb = g_nbr + node * K1;

    int idx[K];
#pragma unroll
    for (int t = 0; t < K; t++) idx[t] = __ldg(nb + t);

    float4 a0 = make_float4(0.f, 0.f, 0.f, 0.f);
    float4 a1 = make_float4(0.f, 0.f, 0.f, 0.f);
#pragma unroll
    for (int t = 0; t < K; t += 2) {
        if (t < cnt) {
            float4 v = *(const float4*)(g_yn + (size_t)idx[t] * FEAT + c4);
            a0.x += v.x; a0.y += v.y; a0.z += v.z; a0.w += v.w;
        }
        if (t + 1 < cnt) {
            float4 v = *(const float4*)(g_yn + (size_t)idx[t + 1] * FEAT + c4);
            a1.x += v.x; a1.y += v.y; a1.z += v.z; a1.w += v.w;
        }
    }
    float inv = (cnt > 0) ? (1.0f / (float)cnt) : 0.f;
    float4 b4 = *(const float4*)(bn + c4);
    float4 s4 = *(const float4*)(g_s + (size_t)node * FEAT + c4);
    float4 o;
    if (cnt > 0) {
        o.x = s4.x + lrelu((a0.x + a1.x) * inv + b4.x);
        o.y = s4.y + lrelu((a0.y + a1.y) * inv + b4.y);
        o.z = s4.z + lrelu((a0.z + a1.z) * inv + b4.z);
        o.w = s4.w + lrelu((a0.w + a1.w) * inv + b4.w);
    } else {
        o = s4;
    }
    *(float4*)(OutH + (size_t)node * FEAT + c4) = o;
}

// ---------------------------------------------------------------------------
// Kernel 4: final GEMM [8192,256]x[256,64] (tf32 mma) + fused log_softmax.
// BM=32, 128 threads (2x2 warps, warp tile 16x32), grid = 256 CTAs.
// ---------------------------------------------------------------------------
__global__ __launch_bounds__(128) void final_kernel(
    const float* __restrict__ W3, const float* __restrict__ b3,
    float* __restrict__ OutP)
{
    constexpr int BM = 32, BN = 64, BK = 16;
    const float* __restrict__ H = (const float*)g_h2;

    __shared__ unsigned sA[BK][BM];
    __shared__ unsigned sB[BK][BN];
    __shared__ float sRes[BM][BN + 1];
    __shared__ float sLse[BM];

    int tid = threadIdx.x;
    int m0 = blockIdx.x * BM;
    int am = tid & 31, ak = (tid >> 5) * 4;       // A: 32 rows x 16 k, 4/thread
    int bn = tid & 63, bk = (tid >> 6) * 8;       // B: 64 rows x 16 k, 8/thread
    const float* pA = H  + (size_t)(m0 + am) * FEAT + ak;
    const float* pB = W3 + (size_t)bn * FEAT + bk;

    int warp = tid >> 5, lane = tid & 31;
    int wm = (warp >> 1) * 16, wn = (warp & 1) * 32;
    int group = lane >> 2, tig = lane & 3;
    int sw = tig << 3;

    float acc[4][4];
#pragma unroll
    for (int j = 0; j < 4; j++)
#pragma unroll
        for (int l = 0; l < 4; l++) acc[j][l] = 0.f;

    for (int k0 = 0; k0 < FEAT; k0 += BK) {
        float4 av  = *(const float4*)(pA + k0);
        float4 b0v = *(const float4*)(pB + k0);
        float4 b1v = *(const float4*)(pB + k0 + 4);
        __syncthreads();
        // A: rows 0..31, swizzle (k&3)<<3 stays < 32
        sA[ak + 0][am ^ 0 ] = f2tf(av.x);  sA[ak + 1][am ^ 8 ] = f2tf(av.y);
        sA[ak + 2][am ^ 16] = f2tf(av.z);  sA[ak + 3][am ^ 24] = f2tf(av.w);
        sB[bk + 0][bn ^ 0 ] = f2tf(b0v.x); sB[bk + 1][bn ^ 8 ] = f2tf(b0v.y);
        sB[bk + 2][bn ^ 16] = f2tf(b0v.z); sB[bk + 3][bn ^ 24] = f2tf(b0v.w);
        sB[bk + 4][bn ^ 0 ] = f2tf(b1v.x); sB[bk + 5][bn ^ 8 ] = f2tf(b1v.y);
        sB[bk + 6][bn ^ 16] = f2tf(b1v.z); sB[bk + 7][bn ^ 24] = f2tf(b1v.w);
        __syncthreads();
#pragma unroll
        for (int kk = 0; kk < BK; kk += 8) {
            int kA = kk + tig;
            unsigned af[4], bf[4][2];
            {
                int r = wm + group;
                af[0] = sA[kA    ][r       ^ sw];
                af[1] = sA[kA    ][(r + 8) ^ sw];
                af[2] = sA[kA + 4][r       ^ sw];
                af[3] = sA[kA + 4][(r + 8) ^ sw];
            }
#pragma unroll
            for (int ni = 0; ni < 4; ni++) {
                int c = (wn + ni * 8 + group) ^ sw;
                bf[ni][0] = sB[kA    ][c];
                bf[ni][1] = sB[kA + 4][c];
            }
#pragma unroll
            for (int ni = 0; ni < 4; ni++)
                mma_tf32(acc[ni], af[0], af[1], af[2], af[3],
                         bf[ni][0], bf[ni][1]);
        }
    }

#pragma unroll
    for (int half = 0; half < 2; half++) {
        int r = wm + group + half * 8;
#pragma unroll
        for (int ni = 0; ni < 4; ni++) {
            int col = wn + ni * 8 + tig * 2;
            sRes[r][col]     = acc[ni][half * 2 + 0] + __ldg(b3 + col);
            sRes[r][col + 1] = acc[ni][half * 2 + 1] + __ldg(b3 + col + 1);
        }
    }
    __syncthreads();

    // log-softmax: 4 threads per row, 16 cols each, combine via 2 shfl_xor
    {
        int row = tid >> 2, q = tid & 3;
        int cbase = q * 16;
        float mx = -1e30f;
#pragma unroll
        for (int c = 0; c < 16; c++) mx = fmaxf(mx, sRes[row][cbase + c]);
        mx = fmaxf(mx, __shfl_xor_sync(0xffffffffu, mx, 1));
        mx = fmaxf(mx, __shfl_xor_sync(0xffffffffu, mx, 2));
        float s = 0.f;
#pragma unroll
        for (int c = 0; c < 16; c++) s += expf(sRes[row][cbase + c] - mx);
        s += __shfl_xor_sync(0xffffffffu, s, 1);
        s += __shfl_xor_sync(0xffffffffu, s, 2);
        if (q == 0) sLse[row] = mx + logf(s);
    }
    __syncthreads();

    for (int idx = tid; idx < BM * 64; idx += 128) {
        int r = idx >> 6, c = idx & 63;
        OutP[(size_t)(m0 + r) * 64 + c] = sRes[r][c] - sLse[r];
    }
}

// ---------------------------------------------------------------------------
extern "C" void kernel_launch(void* const* d_in, const int* in_sizes, int n_in,
                              void* d_out, int out_size) {
    const float* X   = (const float*)d_in[0];
    const int*   A   = (const int*)  d_in[1];
    const float* Wn1 = (const float*)d_in[2];
    const float* bn1 = (const float*)d_in[3];
    const float* Wl1 = (const float*)d_in[4];
    const float* bl1 = (const float*)d_in[5];
    const float* Wn2 = (const float*)d_in[6];
    const float* bn2 = (const float*)d_in[7];
    const float* Wl2 = (const float*)d_in[8];
    const float* bl2 = (const float*)d_in[9];
    const float* W3  = (const float*)d_in[10];
    const float* b3  = (const float*)d_in[11];
    float* out = (float*)d_out;

    float* h1p; cudaGetSymbolAddress((void**)&h1p, g_h1);
    float* h2p; cudaGetSymbolAddress((void**)&h2p, g_h2);

    dim3 ggrid(8, N_NODES / 128);   // 8 n-tiles (4 self + 4 yn) x 64 m-tiles

    // layer 1 GEMM depends only on X -> launch first
    gemm_dual<1><<<ggrid, 256>>>(X, Wl1, bl1, Wn1);
    nbr_kernel<<<N_NODES / 8, 256>>>(A);
    comb_kernel<K1><<<N_NODES / 4, 256>>>(bn1, h1p);

    // layer 2
    gemm_dual<2><<<ggrid, 256>>>(X, Wl2, bl2, Wn2);
    comb_kernel<K2><<<N_NODES / 4, 256>>>(bn2, h2p);

    // classifier + log_softmax
    final_kernel<<<N_NODES / 32, 128>>>(W3, b3, out);
}

// round 15
// speedup vs baseline: 1.1219x; 1.0255x over previous
#include <cuda_runtime.h>
#include <cstdint>
#include <math.h>

#define N_NODES 8192
#define FEAT    256
#define K1      25
#define K2      10

// Scratch (device globals — no allocation allowed)
__device__ int   g_nbr[N_NODES * K1];
__device__ int   g_cnt[N_NODES];
__device__ float g_s [N_NODES * FEAT];   // self branch:  lrelu(A@Wl^T + bl)
__device__ float g_yn[N_NODES * FEAT];   // raw nbr GEMM: A@Wn^T
__device__ float g_h1[N_NODES * FEAT];   // layer-1 output
__device__ float g_h2[N_NODES * FEAT];   // layer-2 output

__device__ __forceinline__ float lrelu(float x) {
    return x > 0.f ? x : 0.01f * x;
}

__device__ __forceinline__ unsigned f2tf(float x) {
    unsigned u;
    asm("cvt.rna.tf32.f32 %0, %1;" : "=r"(u) : "f"(x));
    return u;
}

__device__ __forceinline__ void mma_tf32(float* c,
    unsigned a0, unsigned a1, unsigned a2, unsigned a3,
    unsigned b0, unsigned b1)
{
    asm volatile(
        "mma.sync.aligned.m16n8k8.row.col.f32.tf32.tf32.f32 "
        "{%0,%1,%2,%3}, {%4,%5,%6,%7}, {%8,%9}, {%0,%1,%2,%3};"
        : "+f"(c[0]), "+f"(c[1]), "+f"(c[2]), "+f"(c[3])
        : "r"(a0), "r"(a1), "r"(a2), "r"(a3), "r"(b0), "r"(b1));
}

#define LDM_X4(r0, r1, r2, r3, addr)                                          \
    asm volatile("ldmatrix.sync.aligned.m8n8.x4.shared.b16 {%0,%1,%2,%3}, [%4];" \
        : "=r"(r0), "=r"(r1), "=r"(r2), "=r"(r3) : "r"(addr))

__device__ __forceinline__ void cp16(unsigned dst, const void* src) {
    asm volatile("cp.async.cg.shared.global [%0], [%1], 16;" :: "r"(dst), "l"(src));
}
__device__ __forceinline__ void cp_commit() {
    asm volatile("cp.async.commit_group;" ::: "memory");
}
__device__ __forceinline__ void cp_wait0() {
    asm volatile("cp.async.wait_group 0;" ::: "memory");
}

// ---------------------------------------------------------------------------
// Device function: first-K1 neighbor scan for one node (executed by one warp).
// ---------------------------------------------------------------------------
__device__ __forceinline__ void nbr_scan_warp(const int* __restrict__ A,
                                              int node, int lane)
{
    const int* row = A + (size_t)node * N_NODES;
    int found = 0;
    for (int c = 0; c < N_NODES && found < K1; c += 32) {
        int v = __ldg(row + c + lane);
        unsigned m = __ballot_sync(0xffffffffu, v > 0);
        if (v > 0) {
            int r = found + __popc(m & ((1u << lane) - 1u));
            if (r < K1) g_nbr[node * K1 + r] = c + lane;
        }
        found += __popc(m);
    }
    int cnt = found < K1 ? found : K1;
    if (lane < K1 && lane >= cnt) g_nbr[node * K1 + lane] = 0;  // safe dummy
    if (lane == 0) g_cnt[node] = cnt;
}

// ---------------------------------------------------------------------------
// Kernel 1: N-concatenated dual GEMM (one layer), both halves read the SAME A.
//   blockIdx.x < 4 : self half, W = Wl -> g_s  = lrelu(A@Wl^T + bl)
//   blockIdx.x >= 4: nbr  half, W = Wn -> g_yn = A@Wn^T          (raw)
// BM=128 BN=64 BK=32, 8 warps (4x2), warp tile 32x32, cp.async double buffer.
// Inner loop: ldmatrix.x4 (tf32-as-b16), 4 ldmatrix + 8 mma per k8.
// LAYER==1 additionally carries the neighbor scan: blockIdx.y in [64,192)
// are scan blocks (8 warps = 8 nodes each; 1024 blocks = 8192 nodes), which
// overlap the latency-bound adjacency scan with the GEMM.
// ---------------------------------------------------------------------------
template<int LAYER>
__global__ __launch_bounds__(256) void gemm_dual(
    const float* __restrict__ X,
    const float* __restrict__ Wl, const float* __restrict__ bl,
    const float* __restrict__ Wn, const int* __restrict__ Adj)
{
    constexpr int BM = 128, BN = 64, BK = 32, NIT = FEAT / BK;
    __shared__ __align__(16) unsigned sA[2][BM * BK];
    __shared__ __align__(16) unsigned sB[2][BN * BK];

    int tid = threadIdx.x;
    int warp = tid >> 5, lane = tid & 31;

    if (LAYER == 1 && blockIdx.y >= 64) {
        // ---- neighbor-scan block (uniform per block; no syncthreads used) ----
        int node = (((int)blockIdx.y - 64) * 8 + (int)blockIdx.x) * 8 + warp;
        nbr_scan_warp(Adj, node, lane);
        return;
    }

    bool self = blockIdx.x < 4;
    int n0 = (blockIdx.x & 3) * BN;
    int m0 = blockIdx.y * BM;

    const float* Abase = (LAYER == 1) ? X : (const float*)g_h1;
    const float* W     = self ? Wl : Wn;
    float* Out         = self ? g_s : g_yn;

    // loader mapping: A 4 chunks/thread, B 2 chunks/thread (16B chunks)
    int am  = tid >> 1, akc = (tid & 1) * 4;
    int bn_ = tid >> 2, bkc = (tid & 3) * 2;
    const float* pA = Abase + (size_t)(m0 + am)  * FEAT + akc * 4;
    const float* pB = W     + (size_t)(n0 + bn_) * FEAT + bkc * 4;
    unsigned baseA = (unsigned)__cvta_generic_to_shared(&sA[0][0]);
    unsigned baseB = (unsigned)__cvta_generic_to_shared(&sB[0][0]);
    unsigned dA = baseA + am  * (BK * 4);
    unsigned dB = baseB + bn_ * (BK * 4);
    int aswz = am  & 7, bswz = bn_ & 7;

    // fragment ids
    int wm = (warp >> 1) * 32, wn = (warp & 1) * 32;
    int group = lane >> 2, tig = lane & 3;

    // ldmatrix per-lane row/chunk assignments (swizzle key = lane&7 for all)
    int lrowA = lane & 15;          // row within a 16-row block
    int lselA = lane >> 4;          // 0 -> chunk c, 1 -> chunk c+1
    int lswz  = lane & 7;
    unsigned rowBaseA0 = baseA + (unsigned)((wm +  0 + lrowA) * BK) * 4u;
    unsigned rowBaseA1 = baseA + (unsigned)((wm + 16 + lrowA) * BK) * 4u;
    unsigned rowBaseB  = baseB + (unsigned)((wn + lane) * BK) * 4u;

    float acc[2][4][4];
#pragma unroll
    for (int i = 0; i < 2; i++)
#pragma unroll
        for (int j = 0; j < 4; j++)
#pragma unroll
            for (int l = 0; l < 4; l++) acc[i][j][l] = 0.f;

#define ISSUE(st, k0)                                                          \
    {                                                                          \
        unsigned oa = dA + (st) * (BM * BK * 4);                               \
        const float* ga = pA + (k0);                                           \
        _Pragma("unroll")                                                      \
        for (int j = 0; j < 4; j++)                                            \
            cp16(oa + (((akc + j) ^ aswz) << 4), ga + j * 4);                  \
        unsigned ob = dB + (st) * (BN * BK * 4);                               \
        const float* gb = pB + (k0);                                           \
        _Pragma("unroll")                                                      \
        for (int j = 0; j < 2; j++)                                            \
            cp16(ob + (((bkc + j) ^ bswz) << 4), gb + j * 4);                  \
        cp_commit();                                                           \
    }

    ISSUE(0, 0);

    int st = 0;
    for (int it = 0; it < NIT; it++) {
        cp_wait0();
        __syncthreads();
        if (it + 1 < NIT) ISSUE(st ^ 1, (it + 1) * BK);
        unsigned stA = (unsigned)st * (BM * BK * 4);
        unsigned stB = (unsigned)st * (BN * BK * 4);
#pragma unroll
        for (int kk = 0; kk < BK; kk += 8) {
            int c0 = kk >> 2;
            unsigned af[2][4], bf0[4], bf1[4];
            LDM_X4(af[0][0], af[0][1], af[0][2], af[0][3],
                   rowBaseA0 + stA + (unsigned)(((c0 + lselA) ^ lswz) << 4));
            LDM_X4(af[1][0], af[1][1], af[1][2], af[1][3],
                   rowBaseA1 + stA + (unsigned)(((c0 + lselA) ^ lswz) << 4));
            LDM_X4(bf0[0], bf0[1], bf0[2], bf0[3],
                   rowBaseB + stB + (unsigned)((c0 ^ lswz) << 4));
            LDM_X4(bf1[0], bf1[1], bf1[2], bf1[3],
                   rowBaseB + stB + (unsigned)(((c0 + 1) ^ lswz) << 4));
#pragma unroll
            for (int mi = 0; mi < 2; mi++)
#pragma unroll
                for (int ni = 0; ni < 4; ni++)
                    mma_tf32(acc[mi][ni], af[mi][0], af[mi][1], af[mi][2], af[mi][3],
                             bf0[ni], bf1[ni]);
        }
        st ^= 1;
    }

    // epilogue: self half gets bias+lrelu, yn half is raw
#pragma unroll
    for (int mi = 0; mi < 2; mi++) {
#pragma unroll
        for (int half = 0; half < 2; half++) {
            int row = m0 + wm + mi * 16 + group + half * 8;
#pragma unroll
            for (int ni = 0; ni < 4; ni++) {
                int col = n0 + wn + ni * 8 + tig * 2;
                float v0 = acc[mi][ni][half * 2 + 0];
                float v1 = acc[mi][ni][half * 2 + 1];
                if (self) {
                    v0 = lrelu(v0 + __ldg(bl + col));
                    v1 = lrelu(v1 + __ldg(bl + col + 1));
                }
                *(float2*)(Out + (size_t)row * FEAT + col) = make_float2(v0, v1);
            }
        }
    }
#undef ISSUE
}

// ---------------------------------------------------------------------------
// Kernel 2: gather-mean over first min(cnt,K) rows of g_yn + bias + lrelu,
// combined with the self branch:  h = g_s + (cnt>0 ? lrelu(mean + bn) : 0).
// 4 nodes / 256-thread block, float4/thread, dual accumulators.
// ---------------------------------------------------------------------------
template <int K>
__global__ __launch_bounds__(256) void comb_kernel(
    const float* __restrict__ bn, float* __restrict__ OutH)
{
    int node = blockIdx.x * 4 + (threadIdx.x >> 6);
    int c4   = (threadIdx.x & 63) << 2;
    int cnt = g_cnt[node]; if (cnt > K) cnt = K;
    const int* nb = g_nbr + node * K1;

    int idx[K];
#pragma unroll
    for (int t = 0; t < K; t++) idx[t] = __ldg(nb + t);

    float4 a0 = make_float4(0.f, 0.f, 0.f, 0.f);
    float4 a1 = make_float4(0.f, 0.f, 0.f, 0.f);
#pragma unroll
    for (int t = 0; t < K; t += 2) {
        if (t < cnt) {
            float4 v = *(const float4*)(g_yn + (size_t)idx[t] * FEAT + c4);
            a0.x += v.x; a0.y += v.y; a0.z += v.z; a0.w += v.w;
        }
        if (t + 1 < cnt) {
            float4 v = *(const float4*)(g_yn + (size_t)idx[t + 1] * FEAT + c4);
            a1.x += v.x; a1.y += v.y; a1.z += v.z; a1.w += v.w;
        }
    }
    float inv = (cnt > 0) ? (1.0f / (float)cnt) : 0.f;
    float4 b4 = *(const float4*)(bn + c4);
    float4 s4 = *(const float4*)(g_s + (size_t)node * FEAT + c4);
    float4 o;
    if (cnt > 0) {
        o.x = s4.x + lrelu((a0.x + a1.x) * inv + b4.x);
        o.y = s4.y + lrelu((a0.y + a1.y) * inv + b4.y);
        o.z = s4.z + lrelu((a0.z + a1.z) * inv + b4.z);
        o.w = s4.w + lrelu((a0.w + a1.w) * inv + b4.w);
    } else {
        o = s4;
    }
    *(float4*)(OutH + (size_t)node * FEAT + c4) = o;
}

// ---------------------------------------------------------------------------
// Kernel 3: final GEMM [8192,256]x[256,64] (tf32 mma) + fused log_softmax.
// BM=32, 128 threads (2x2 warps, warp tile 16x32), grid = 256 CTAs.
// ---------------------------------------------------------------------------
__global__ __launch_bounds__(128) void final_kernel(
    const float* __restrict__ W3, const float* __restrict__ b3,
    float* __restrict__ OutP)
{
    constexpr int BM = 32, BN = 64, BK = 16;
    const float* __restrict__ H = (const float*)g_h2;

    __shared__ unsigned sA[BK][BM];
    __shared__ unsigned sB[BK][BN];
    __shared__ float sRes[BM][BN + 1];
    __shared__ float sLse[BM];

    int tid = threadIdx.x;
    int m0 = blockIdx.x * BM;
    int am = tid & 31, ak = (tid >> 5) * 4;       // A: 32 rows x 16 k, 4/thread
    int bn = tid & 63, bk = (tid >> 6) * 8;       // B: 64 rows x 16 k, 8/thread
    const float* pA = H  + (size_t)(m0 + am) * FEAT + ak;
    const float* pB = W3 + (size_t)bn * FEAT + bk;

    int warp = tid >> 5, lane = tid & 31;
    int wm = (warp >> 1) * 16, wn = (warp & 1) * 32;
    int group = lane >> 2, tig = lane & 3;
    int sw = tig << 3;

    float acc[4][4];
#pragma unroll
    for (int j = 0; j < 4; j++)
#pragma unroll
        for (int l = 0; l < 4; l++) acc[j][l] = 0.f;

    for (int k0 = 0; k0 < FEAT; k0 += BK) {
        float4 av  = *(const float4*)(pA + k0);
        float4 b0v = *(const float4*)(pB + k0);
        float4 b1v = *(const float4*)(pB + k0 + 4);
        __syncthreads();
        sA[ak + 0][am ^ 0 ] = f2tf(av.x);  sA[ak + 1][am ^ 8 ] = f2tf(av.y);
        sA[ak + 2][am ^ 16] = f2tf(av.z);  sA[ak + 3][am ^ 24] = f2tf(av.w);
        sB[bk + 0][bn ^ 0 ] = f2tf(b0v.x); sB[bk + 1][bn ^ 8 ] = f2tf(b0v.y);
        sB[bk + 2][bn ^ 16] = f2tf(b0v.z); sB[bk + 3][bn ^ 24] = f2tf(b0v.w);
        sB[bk + 4][bn ^ 0 ] = f2tf(b1v.x); sB[bk + 5][bn ^ 8 ] = f2tf(b1v.y);
        sB[bk + 6][bn ^ 16] = f2tf(b1v.z); sB[bk + 7][bn ^ 24] = f2tf(b1v.w);
        __syncthreads();
#pragma unroll
        for (int kk = 0; kk < BK; kk += 8) {
            int kA = kk + tig;
            unsigned af[4], bf[4][2];
            {
                int r = wm + group;
                af[0] = sA[kA    ][r       ^ sw];
                af[1] = sA[kA    ][(r + 8) ^ sw];
                af[2] = sA[kA + 4][r       ^ sw];
                af[3] = sA[kA + 4][(r + 8) ^ sw];
            }
#pragma unroll
            for (int ni = 0; ni < 4; ni++) {
                int c = (wn + ni * 8 + group) ^ sw;
                bf[ni][0] = sB[kA    ][c];
                bf[ni][1] = sB[kA + 4][c];
            }
#pragma unroll
            for (int ni = 0; ni < 4; ni++)
                mma_tf32(acc[ni], af[0], af[1], af[2], af[3],
                         bf[ni][0], bf[ni][1]);
        }
    }

#pragma unroll
    for (int half = 0; half < 2; half++) {
        int r = wm + group + half * 8;
#pragma unroll
        for (int ni = 0; ni < 4; ni++) {
            int col = wn + ni * 8 + tig * 2;
            sRes[r][col]     = acc[ni][half * 2 + 0] + __ldg(b3 + col);
            sRes[r][col + 1] = acc[ni][half * 2 + 1] + __ldg(b3 + col + 1);
        }
    }
    __syncthreads();

    // log-softmax: 4 threads per row, 16 cols each, combine via 2 shfl_xor
    {
        int row = tid >> 2, q = tid & 3;
        int cbase = q * 16;
        float mx = -1e30f;
#pragma unroll
        for (int c = 0; c < 16; c++) mx = fmaxf(mx, sRes[row][cbase + c]);
        mx = fmaxf(mx, __shfl_xor_sync(0xffffffffu, mx, 1));
        mx = fmaxf(mx, __shfl_xor_sync(0xffffffffu, mx, 2));
        float s = 0.f;
#pragma unroll
        for (int c = 0; c < 16; c++) s += expf(sRes[row][cbase + c] - mx);
        s += __shfl_xor_sync(0xffffffffu, s, 1);
        s += __shfl_xor_sync(0xffffffffu, s, 2);
        if (q == 0) sLse[row] = mx + logf(s);
    }
    __syncthreads();

    for (int idx = tid; idx < BM * 64; idx += 128) {
        int r = idx >> 6, c = idx & 63;
        OutP[(size_t)(m0 + r) * 64 + c] = sRes[r][c] - sLse[r];
    }
}

// ---------------------------------------------------------------------------
extern "C" void kernel_launch(void* const* d_in, const int* in_sizes, int n_in,
                              void* d_out, int out_size) {
    const float* X   = (const float*)d_in[0];
    const int*   A   = (const int*)  d_in[1];
    const float* Wn1 = (const float*)d_in[2];
    const float* bn1 = (const float*)d_in[3];
    const float* Wl1 = (const float*)d_in[4];
    const float* bl1 = (const float*)d_in[5];
    const float* Wn2 = (const float*)d_in[6];
    const float* bn2 = (const float*)d_in[7];
    const float* Wl2 = (const float*)d_in[8];
    const float* bl2 = (const float*)d_in[9];
    const float* W3  = (const float*)d_in[10];
    const float* b3  = (const float*)d_in[11];
    float* out = (float*)d_out;

    float* h1p; cudaGetSymbolAddress((void**)&h1p, g_h1);
    float* h2p; cudaGetSymbolAddress((void**)&h2p, g_h2);

    // layer 1: GEMM tiles (by 0..63) + neighbor-scan blocks (by 64..191)
    gemm_dual<1><<<dim3(8, 192), 256>>>(X, Wl1, bl1, Wn1, A);
    comb_kernel<K1><<<N_NODES / 4, 256>>>(bn1, h1p);

    // layer 2
    gemm_dual<2><<<dim3(8, 64), 256>>>(X, Wl2, bl2, Wn2, A);
    comb_kernel<K2><<<N_NODES / 4, 256>>>(bn2, h2p);

    // classifier + log_softmax
    final_kernel<<<N_NODES / 32, 128>>>(W3, b3, out);
}